// round 16
// baseline (speedup 1.0000x reference)
#include <cuda_runtime.h>
#include <cuda_bf16.h>

#define B_  256
#define T_  2048
#define BT  (B_ * T_)
#define NBLK 152
#define NW   150

__device__ float4 g_pp[BT + 16 * B_];  // (10*pet, 0.5*pet, p-pet, 0) [t][b], padded
__device__ float4 g_w[(T_ / 2) * B_];  // (wu0,wd0,wu1,wd1) per t-pair [t/2][b]
__device__ float  g_params[BT * 8];    // row-major [r][8]
__device__ int    g_ttdone[32];        // transpose tiles done per 64-step chunk (==8 ready)

__device__ __forceinline__ float tanhA(float x) {
    float r; asm("tanh.approx.f32 %0, %1;" : "=f"(r) : "f"(x)); return r;
}
__device__ __forceinline__ float heav(float x10) {
    return fmaf(0.5f, tanhA(x10), 0.5f);
}
__device__ __forceinline__ float sigm1(float x) {
    return fmaf(0.5f, tanhA(0.5f * x), 0.5f);
}
__device__ __forceinline__ unsigned int packbf(float lo, float hi) {
    unsigned int r;
    asm("cvt.rn.bf16x2.f32 %0, %1, %2;" : "=r"(r) : "f"(hi), "f"(lo));
    return r;
}
__device__ __forceinline__ void mma16816(float& c0, float& c1, float& c2, float& c3,
                                         unsigned int a0, unsigned int a1,
                                         unsigned int a2, unsigned int a3,
                                         unsigned int b0, unsigned int b1) {
    asm volatile(
        "mma.sync.aligned.m16n8k16.row.col.f32.bf16.bf16.f32 "
        "{%0,%1,%2,%3},{%4,%5,%6,%7},{%8,%9},{%0,%1,%2,%3};\n"
        : "+f"(c0), "+f"(c1), "+f"(c2), "+f"(c3)
        : "r"(a0), "r"(a1), "r"(a2), "r"(a3), "r"(b0), "r"(b1));
}

__device__ __forceinline__ float tanhT(const char* tblc, float y) {
    float yc = fminf(fmaxf(y, -8.0f), 7.99609375f);
    float u  = yc + 49152.0f;
    unsigned ub  = __float_as_uint(u);
    unsigned off = ((ub & 0x7FFFFFu) - 4192256u) * 8u;
    float2 vd = *reinterpret_cast<const float2*>(tblc + off);
    float x0 = u - 49152.0f;
    float t  = yc - x0;
    return fmaf(t, vd.y, vd.x);
}

// ---- reset: zero chunk flags (tiny) ------------------------------------------
__global__ void reset_kernel() {
    if (threadIdx.x < 32) g_ttdone[threadIdx.x] = 0;
}

// ======== scan macros (R13, bit-identical math) ================================
#define SCAN_B2()                                                          \
  { float t3     = tanhA(fmaf(-10.0f, wd, y10B));                          \
    float inner2 = fmaf(t3, wd - yB, wd + yB);                             \
    float wdps   = wd + sd2B;                                              \
    wd = fmaf(-vB, inner2, wdps); }

#define SCAN_B1()                                                          \
  { float tw    = tanhA(fmaf(-10.0f, wl, rp10A));                          \
    float inner = fmaf(tw, wl - rpA, wl + rpA);                            \
    float wlpp  = wl + ppvzA;                                              \
    float et2   = uA * inner;                                              \
    wl = fmaf(-uA, inner, wlpp);                                           \
    float y   = rpA - et2;                                                 \
    float y10 = 10.0f * y;                                                 \
    float ty  = tanhA(y10);                                                \
    yB = y; y10B = y10; vB = fmaf(0.25f, ty, 0.25f); sd2B = ppvzA - et2; }

#define SCAN_A(QQ)                                                         \
  { float t1  = tanhA(fmaf(-10.0f, wu, (QQ).x));                           \
    float hd1 = fmaf(-0.5f, wu, (QQ).y);                                   \
    float z   = fmaf(t1, hd1, hd1);                                        \
    float wupp = wu + (QQ).z;                                              \
    wuS3 = wuS2; wuS2 = wuS1; wuS1 = wupp + z; wu = wuS1;                  \
    float tz  = tanhA(10.0f * z);                                          \
    float hz  = 0.5f * z;                                                  \
    float rp  = fmaf(tz, hz, hz);                                          \
    float rp10 = 10.0f * rp;                                               \
    float trp = tanhA(rp10);                                               \
    uA = fmaf(0.25f, trp, 0.25f);                                          \
    rpA = rp; rp10A = rp10; ppvzA = (QQ).z + z; }

#define IBODY(I, SLOT, STORE)                                              \
  { float4 qq = q##SLOT;                                                   \
    q##SLOT = pp[((I) + 8) * B_];                                          \
    float a_arg = fmaf(-10.0f, wu, qq.x);                                  \
    float b1arg = fmaf(-10.0f, wl, rp10A);                                 \
    float b2arg = fmaf(-10.0f, wd, y10B);                                  \
    float t1 = tanhA(a_arg);                                               \
    float tw = tanhA(b1arg);                                               \
    float t3 = tanhA(b2arg);                                               \
    float hd1  = fmaf(-0.5f, wu, qq.y);                                    \
    float wupp = wu + qq.z;                                                \
    float wdps = wd + sd2B;                                                \
    float wlpp = wl + ppvzA;                                               \
    float inner2 = fmaf(t3, wd - yB, wd + yB);                             \
    float wdP = wd;                                                        \
    wd = fmaf(-vB, inner2, wdps);                                          \
    float inner = fmaf(tw, wl - rpA, wl + rpA);                            \
    float et2   = uA * inner;                                              \
    wl = fmaf(-uA, inner, wlpp);                                           \
    float z = fmaf(t1, hd1, hd1);                                          \
    float y = rpA - et2;                                                   \
    float y10n = 10.0f * y;                                                \
    float tz = tanhT(tblc, 10.0f * z);                                     \
    float ty = tanhT(tblc, y10n);                                          \
    STORE                                                                  \
    sd2B = ppvzA - et2;                                                    \
    yB = y; y10B = y10n;                                                   \
    float wuN = wupp + z;                                                  \
    float hz  = 0.5f * z;                                                  \
    wuS3 = wuS2; wuS2 = wuS1; wuS1 = wuN; wu = wuN;                        \
    float rp   = fmaf(tz, hz, hz);                                         \
    vB = fmaf(0.25f, ty, 0.25f);                                           \
    float rp10n = 10.0f * rp;                                              \
    float trp = tanhT(tblc, rp10n);                                        \
    rpA = rp; rp10A = rp10n; ppvzA = qq.z + z;                             \
    uA = fmaf(0.25f, trp, 0.25f); }

#define NOSTORE
#define DOSTORE(I) wp[(((I) - 2) >> 1) * B_] = make_float4(wuS3, wdP, wuS2, wd);

#define GROUP8(BASE)                                                       \
    IBODY((BASE) + 0, 0, NOSTORE)                                          \
    IBODY((BASE) + 1, 1, DOSTORE((BASE) + 1))                              \
    IBODY((BASE) + 2, 2, NOSTORE)                                          \
    IBODY((BASE) + 3, 3, DOSTORE((BASE) + 3))                              \
    IBODY((BASE) + 4, 4, NOSTORE)                                          \
    IBODY((BASE) + 5, 5, DOSTORE((BASE) + 5))                              \
    IBODY((BASE) + 6, 6, NOSTORE)                                          \
    IBODY((BASE) + 7, 7, DOSTORE((BASE) + 7))

// ---- fused main: blocks 0,1 scan ; blocks 2..151 transpose + MLP -------------
__global__ void __launch_bounds__(256)
main_kernel(const float* __restrict__ in,
            const float* __restrict__ w1v,
            const float* __restrict__ b1v,
            const float* __restrict__ w2v,
            const float* __restrict__ b2v,
            const float* __restrict__ w3v,
            const float* __restrict__ b3v) {
    __shared__ union {
        float4 tile[64][33];
        struct {
            uint2 W1[32 * 32];
            uint2 W2[16 * 8 * 32];     // scan blocks: tanh table lives here
            uint2 W3[4 * 32];
            float B1[256];
            float B2[64];
            float B3[8];
        } m;
    } sh;
    int tid = threadIdx.x;

    if (blockIdx.x < 2) {
        // ===================== scan =====================
        float2* tbl = reinterpret_cast<float2*>(sh.m.W2);
        for (int idx = tid; idx < 4096; idx += blockDim.x) {
            float x = -8.0f + (float)idx * (1.0f / 256.0f);
            float v = tanhA(x);
            tbl[idx] = make_float2(v, fmaf(-v, v, 1.0f));
        }
        __syncthreads();
        if (tid >= 128) return;
        const char* tblc = reinterpret_cast<const char*>(tbl);
        int b = blockIdx.x * 128 + tid;
        const float4* __restrict__ pp = g_pp + b;
        float4* __restrict__ wp = g_w + b;
        volatile int* ttd = g_ttdone;

        // wait for chunks 0 and 1 (covers prologue + chunk-0 prefetch reach)
        while (ttd[0] < 8 || ttd[1] < 8) {}
        __threadfence();

        float wu = 0.0f, wl = 0.0f, wd = 0.0f;
        float wuS1 = 0.0f, wuS2 = 0.0f, wuS3 = 0.0f;
        float rpA = 0.0f, rp10A = 0.0f, uA = 0.25f, ppvzA = 0.0f;
        float yB = 0.0f, y10B = 0.0f, vB = 0.25f, sd2B = 0.0f;

        float4 q0 = pp[0 * B_];
        float4 q1 = pp[1 * B_];
        float4 q2 = pp[2 * B_];
        float4 q3 = pp[3 * B_];
        float4 q4 = pp[4 * B_];
        float4 q5 = pp[5 * B_];
        float4 q6 = pp[6 * B_];
        float4 q7 = pp[7 * B_];

        // prologue: bodies 0 (A), 1 (B1+A)
        { float4 qq = q0; q0 = pp[8 * B_]; SCAN_A(qq); }
        { float4 qq = q1; q1 = pp[9 * B_]; SCAN_B1(); SCAN_A(qq); }
        // chunk 0 remainder: bodies 2..7
        IBODY(2, 2, NOSTORE)
        IBODY(3, 3, DOSTORE(3))
        IBODY(4, 4, NOSTORE)
        IBODY(5, 5, DOSTORE(5))
        IBODY(6, 6, NOSTORE)
        IBODY(7, 7, DOSTORE(7))
        GROUP8(8)  GROUP8(16) GROUP8(24) GROUP8(32)
        GROUP8(40) GROUP8(48) GROUP8(56)

        // chunks 1..31: one poll per chunk, inner region straight-line
        for (int c = 1; c < 32; ++c) {
            int need = (c + 1 < 32) ? c + 1 : 31;
            while (ttd[need] < 8) {}
            __threadfence();
            int base = c * 64;
            GROUP8(base +  0) GROUP8(base +  8)
            GROUP8(base + 16) GROUP8(base + 24)
            GROUP8(base + 32) GROUP8(base + 40)
            GROUP8(base + 48) GROUP8(base + 56)
        }

        // epilogue: steps 2046, 2047
        SCAN_B2();
        float wd2046 = wd;
        SCAN_B1();
        SCAN_B2();
        wp[1023 * B_] = make_float4(wuS2, wd2046, wuS1, wd);
        return;
    }

    // ===================== worker blocks =====================
    int j = blockIdx.x - 2;              // 0..149
    const float4* in4 = reinterpret_cast<const float4*>(in);

    // ---- phase T: streaming-coalesced transpose (time-major tile order) ----
    for (int ii = j; ii < 256; ii += NW) {
        int bt = ii & 7, tt = ii >> 3;
        int b0 = bt * 32, t0 = tt * 64;
        int warp = tid >> 5, lane = tid & 31;
#pragma unroll
        for (int s = 0; s < 4; ++s) {
            int bl = warp * 4 + s;
            long base4 = ((long)(b0 + bl) * 2048 + t0) * 5;
#pragma unroll
            for (int jj = 0; jj < 10; ++jj) {
                int idx = jj * 32 + lane;
                float4 q = in4[base4 + idx];
                int m   = idx / 5;
                int rem = idx - m * 5;
                if (rem == 0) {
                    sh.tile[m][bl] = make_float4(10.0f * q.x, 0.5f * q.x, q.z - q.x, 0.0f);
                }
            }
        }
        __syncthreads();
#pragma unroll
        for (int p = 0; p < 8; ++p) {
            int t_loc = (tid >> 5) + p * 8;
            int b_loc = tid & 31;
            g_pp[(t0 + t_loc) * B_ + b0 + b_loc] = sh.tile[t_loc][b_loc];
        }
        __threadfence();
        __syncthreads();
        if (tid == 0) atomicAdd(&g_ttdone[tt], 1);
        __syncthreads();
    }

    // ---- phase M: MLP (weights packed straight into this block's smem) ----
    for (int i = tid; i < 32 * 32; i += 256) {
        int lane = i & 31, nt = i >> 5;
        int g = lane >> 2, tig = lane & 3;
        int n = nt * 8 + g;
        float e0 = w1v[(2 * tig) * 256 + n];
        float e1 = w1v[(2 * tig + 1) * 256 + n];
        int k2 = 2 * tig + 8, k3 = 2 * tig + 9;
        float e2 = (k2 < 15) ? w1v[k2 * 256 + n] : 0.0f;
        float e3 = (k3 < 15) ? w1v[k3 * 256 + n] : 0.0f;
        sh.m.W1[i] = make_uint2(packbf(e0, e1), packbf(e2, e3));
    }
    for (int i = tid; i < 16 * 8 * 32; i += 256) {
        int lane = i & 31;
        int nt = (i >> 5) & 7;
        int kc = i >> 8;
        int g = lane >> 2, tig = lane & 3;
        int n = nt * 8 + g;
        int k0 = kc * 16 + 2 * tig;
        sh.m.W2[i] = make_uint2(packbf(w2v[k0 * 64 + n], w2v[(k0 + 1) * 64 + n]),
                                packbf(w2v[(k0 + 8) * 64 + n], w2v[(k0 + 9) * 64 + n]));
    }
    for (int i = tid; i < 4 * 32; i += 256) {
        int lane = i & 31;
        int kc = i >> 5;
        int g = lane >> 2, tig = lane & 3;
        int k0 = kc * 16 + 2 * tig;
        sh.m.W3[i] = make_uint2(packbf(w3v[k0 * 8 + g], w3v[(k0 + 1) * 8 + g]),
                                packbf(w3v[(k0 + 8) * 8 + g], w3v[(k0 + 9) * 8 + g]));
    }
    if (tid < 256) sh.m.B1[tid] = b1v[tid];
    if (tid < 64)  sh.m.B2[tid] = b2v[tid];
    if (tid < 8)   sh.m.B3[tid] = b3v[tid];
    __syncthreads();

    int warp = tid >> 5;
    int lane = tid & 31;
    int g    = lane >> 2, tig = lane & 3;
    int wg   = j * 8 + warp;

    for (int tile = wg; tile < 32768; tile += NW * 8) {
        int r0 = tile * 16 + g;
        int r1 = r0 + 8;

        unsigned int A0, A1, A2, A3;
        {
            const float* q0p = in + r0 * 20 + 5;
            const float* q1p = in + r1 * 20 + 5;
            float x0 = q0p[2 * tig],     x1 = q0p[2 * tig + 1];
            float y0 = q1p[2 * tig],     y1 = q1p[2 * tig + 1];
            float x2 = q0p[2 * tig + 8];
            float y2 = q1p[2 * tig + 8];
            float x3 = (tig < 3) ? q0p[2 * tig + 9] : 0.0f;
            float y3 = (tig < 3) ? q1p[2 * tig + 9] : 0.0f;
            A0 = packbf(x0, x1); A1 = packbf(y0, y1);
            A2 = packbf(x2, x3); A3 = packbf(y2, y3);
        }

        unsigned int h1a[16][4];
#pragma unroll
        for (int nt = 0; nt < 32; ++nt) {
            uint2 w = sh.m.W1[nt * 32 + lane];
            float c0 = 0.f, c1 = 0.f, c2 = 0.f, c3 = 0.f;
            mma16816(c0, c1, c2, c3, A0, A1, A2, A3, w.x, w.y);
            int   n0  = nt * 8 + 2 * tig;
            float bb0 = sh.m.B1[n0], bb1 = sh.m.B1[n0 + 1];
            c0 = tanhA(c0 + bb0); c1 = tanhA(c1 + bb1);
            c2 = tanhA(c2 + bb0); c3 = tanhA(c3 + bb1);
            h1a[nt >> 1][(nt & 1) * 2 + 0] = packbf(c0, c1);
            h1a[nt >> 1][(nt & 1) * 2 + 1] = packbf(c2, c3);
        }

        float acc[8][4];
#pragma unroll
        for (int nt = 0; nt < 8; ++nt) { acc[nt][0] = acc[nt][1] = acc[nt][2] = acc[nt][3] = 0.0f; }
#pragma unroll
        for (int kc = 0; kc < 16; ++kc) {
#pragma unroll
            for (int nt = 0; nt < 8; ++nt) {
                uint2 w = sh.m.W2[(kc * 8 + nt) * 32 + lane];
                mma16816(acc[nt][0], acc[nt][1], acc[nt][2], acc[nt][3],
                         h1a[kc][0], h1a[kc][1], h1a[kc][2], h1a[kc][3], w.x, w.y);
            }
        }
        unsigned int h2a[4][4];
#pragma unroll
        for (int nt = 0; nt < 8; ++nt) {
            int   n0  = nt * 8 + 2 * tig;
            float bb0 = sh.m.B2[n0], bb1 = sh.m.B2[n0 + 1];
            float c0 = tanhA(acc[nt][0] + bb0), c1 = tanhA(acc[nt][1] + bb1);
            float c2 = tanhA(acc[nt][2] + bb0), c3 = tanhA(acc[nt][3] + bb1);
            h2a[nt >> 1][(nt & 1) * 2 + 0] = packbf(c0, c1);
            h2a[nt >> 1][(nt & 1) * 2 + 1] = packbf(c2, c3);
        }

        float p0 = 0.f, p1 = 0.f, p2 = 0.f, p3 = 0.f;
#pragma unroll
        for (int kc = 0; kc < 4; ++kc) {
            uint2 w = sh.m.W3[kc * 32 + lane];
            mma16816(p0, p1, p2, p3, h2a[kc][0], h2a[kc][1], h2a[kc][2], h2a[kc][3], w.x, w.y);
        }
        int   n0  = 2 * tig;
        float bb0 = sh.m.B3[n0], bb1 = sh.m.B3[n0 + 1];
        p0 = sigm1(p0 + bb0);
        p1 = sigm1(p1 + bb1);
        p2 = sigm1(p2 + bb0);
        p3 = sigm1(p3 + bb1);
        *reinterpret_cast<float2*>(&g_params[r0 * 8 + n0]) = make_float2(p0, p1);
        *reinterpret_cast<float2*>(&g_params[r1 * 8 + n0]) = make_float2(p2, p3);
    }
}

// ---- final pointwise: runoff + partition (reference's swapped args!) ----------
__global__ void final_kernel(const float* __restrict__ in, float* __restrict__ out) {
    int r = blockIdx.x * 256 + threadIdx.x;     // r = b*T + t
    int b = r >> 11, t = r & 2047;
    float4 wv = g_w[(t >> 1) * B_ + b];
    float wu = (t & 1) ? wv.z : wv.x;
    float wd = (t & 1) ? wv.w : wv.y;
    float p  = in[r * 20 + 2];
    float4 q0 = *reinterpret_cast<const float4*>(&g_params[r * 8]);
    float4 q1 = *reinterpret_cast<const float4*>(&g_params[r * 8 + 4]);
    float wum = q0.x, wlm = q0.y, wdm = q0.z, bb = q0.w;
    float cc  = q1.x, k1 = q1.y, k2 = q1.z, k3 = q1.w;

    float wum_s = wum * 19.9f + 0.1f;
    float wlm_s = wdm * 30.0f + 60.0f;   // inner wlm <- outer wdm
    float wdm_s = wlm * 60.0f + 60.0f;   // inner wdm <- outer wlm
    float c_s   = cc * 0.19f + 0.01f;
    float b_s   = bb * 0.3f + 0.1f;
    float wt    = wum_s + wlm_s + wdm_s;
    float iwt   = __frcp_rn(wt);
    float u = wu * iwt;                  // inner wu
    float v = wd * iwt;                  // inner wl <- outer wd
    float s = c_s * u * u + b_s * v * v;
    float d = p - s;
    float runoff = heav(10.0f * d) * d;

    float k1s = k1 * 0.69f + 0.01f;
    float k2s = k2 * 0.69f + 0.01f;
    float k3s = k3 * 0.89f + 0.01f;
    float sr  = k1s * runoff;
    float itf = k2s * (runoff - sr);
    float bf  = k3s * (runoff - sr - itf);
    out[r] = sr + 0.5f * itf + 0.25f * bf;
}

extern "C" void kernel_launch(void* const* d_in, const int* in_sizes, int n_in,
                              void* d_out, int out_size) {
    const float* in  = (const float*)d_in[0];
    const float* w1  = (const float*)d_in[1];
    const float* b1  = (const float*)d_in[2];
    const float* w2  = (const float*)d_in[3];
    const float* b2  = (const float*)d_in[4];
    const float* w3  = (const float*)d_in[5];
    const float* b3  = (const float*)d_in[6];
    float* out = (float*)d_out;
    reset_kernel<<<1, 32>>>();
    main_kernel<<<NBLK, 256>>>(in, w1, b1, w2, b2, w3, b3);
    final_kernel<<<2048, 256>>>(in, out);
}

// round 17
// speedup vs baseline: 1.2124x; 1.2124x over previous
#include <cuda_runtime.h>
#include <cuda_bf16.h>

#define B_  256
#define T_  2048
#define BT  (B_ * T_)
#define NBLK 152

__device__ float4 g_pp[BT + 8 * B_];   // (10*pet, 0.5*pet, p-pet, p) [t][b], padded
__device__ float  g_p[BT];             // p, dense r-major
__device__ float4 g_w[(T_ / 2) * B_];  // (wu0,wd0,wu1,wd1) per t-pair [t/2][b]
__device__ float  g_params[BT * 8];    // row-major [r][8]
__device__ uint2  g_W1p[32 * 32];
__device__ uint2  g_W2p[16 * 8 * 32];
__device__ uint2  g_W3p[4 * 32];

__device__ __forceinline__ float tanhA(float x) {
    float r; asm("tanh.approx.f32 %0, %1;" : "=f"(r) : "f"(x)); return r;
}
__device__ __forceinline__ float heav(float x10) {   // h given 10*x
    return fmaf(0.5f, tanhA(x10), 0.5f);
}
__device__ __forceinline__ float sigm1(float x) {
    return fmaf(0.5f, tanhA(0.5f * x), 0.5f);
}
__device__ __forceinline__ unsigned int packbf(float lo, float hi) {
    unsigned int r;
    asm("cvt.rn.bf16x2.f32 %0, %1, %2;" : "=r"(r) : "f"(hi), "f"(lo));
    return r;
}
__device__ __forceinline__ void mma16816(float& c0, float& c1, float& c2, float& c3,
                                         unsigned int a0, unsigned int a1,
                                         unsigned int a2, unsigned int a3,
                                         unsigned int b0, unsigned int b1) {
    asm volatile(
        "mma.sync.aligned.m16n8k16.row.col.f32.bf16.bf16.f32 "
        "{%0,%1,%2,%3},{%4,%5,%6,%7},{%8,%9},{%0,%1,%2,%3};\n"
        : "+f"(c0), "+f"(c1), "+f"(c2), "+f"(c3)
        : "r"(a0), "r"(a1), "r"(a2), "r"(a3), "r"(b0), "r"(b1));
}

// tanh via SMEM table (4096 entries over [-8,8), h=1/256) + derivative interp.
__device__ __forceinline__ float tanhT(const char* tblc, float y) {
    float yc = fminf(fmaxf(y, -8.0f), 7.99609375f);
    float u  = yc + 49152.0f;
    unsigned ub  = __float_as_uint(u);
    unsigned off = ((ub & 0x7FFFFFu) - 4192256u) * 8u;
    float2 vd = *reinterpret_cast<const float2*>(tblc + off);
    float x0 = u - 49152.0f;
    float t  = yc - x0;
    return fmaf(t, vd.y, vd.x);
}

// ---- prep: streaming transpose (512 blocks, 32b x 32t tiles) + weights --------
__global__ void prep_kernel(const float* __restrict__ in,
                            const float* __restrict__ w1,
                            const float* __restrict__ w2,
                            const float* __restrict__ w3) {
    int bid = blockIdx.x;
    int tid = threadIdx.x;
    if (bid < 512) {
        __shared__ float4 tile[32][33];        // [t_loc][b_loc]
        int bt = bid & 7;                      // basin tile 0..7   (32 basins)
        int tt = bid >> 3;                     // time tile  0..63  (32 steps)
        int b0 = bt * 32, t0 = tt * 32;
        const float4* in4 = reinterpret_cast<const float4*>(in);
        int warp = tid >> 5, lane = tid & 31;
#pragma unroll
        for (int s = 0; s < 4; ++s) {
            int bl = warp * 4 + s;             // 0..31
            long base4 = ((long)(b0 + bl) * 2048 + t0) * 5;
#pragma unroll
            for (int j = 0; j < 5; ++j) {
                int idx = j * 32 + lane;       // 0..159
                float4 q = in4[base4 + idx];
                int m   = idx / 5;
                int rem = idx - m * 5;
                if (rem == 0) {
                    tile[m][bl] = make_float4(10.0f * q.x, 0.5f * q.x, q.z - q.x, q.z);
                }
            }
        }
        __syncthreads();
        // transposed store (coalesced over basins)
#pragma unroll
        for (int p = 0; p < 4; ++p) {
            int t_loc = (tid >> 5) + p * 8;
            int b_loc = tid & 31;
            g_pp[(t0 + t_loc) * B_ + b0 + b_loc] = tile[t_loc][b_loc];
        }
        // dense p store (r-major, float4 per thread)
        {
            int b_loc = tid >> 3;              // 0..31
            int tc    = (tid & 7) * 4;         // 0..28
            float4 pv = make_float4(tile[tc + 0][b_loc].w, tile[tc + 1][b_loc].w,
                                    tile[tc + 2][b_loc].w, tile[tc + 3][b_loc].w);
            *reinterpret_cast<float4*>(&g_p[(b0 + b_loc) * 2048 + t0 + tc]) = pv;
        }
        return;
    }
    // weight packing (one block)
    for (int i = tid; i < 32 * 32; i += 256) {           // W1 (15x256), k-pad to 16
        int lane = i & 31, nt = i >> 5;
        int g = lane >> 2, tig = lane & 3;
        int n = nt * 8 + g;
        float e0 = w1[(2 * tig) * 256 + n];
        float e1 = w1[(2 * tig + 1) * 256 + n];
        int k2 = 2 * tig + 8, k3 = 2 * tig + 9;
        float e2 = (k2 < 15) ? w1[k2 * 256 + n] : 0.0f;
        float e3 = (k3 < 15) ? w1[k3 * 256 + n] : 0.0f;
        g_W1p[i] = make_uint2(packbf(e0, e1), packbf(e2, e3));
    }
    for (int i = tid; i < 16 * 8 * 32; i += 256) {       // W2 (256x64)
        int lane = i & 31;
        int nt = (i >> 5) & 7;
        int kc = i >> 8;
        int g = lane >> 2, tig = lane & 3;
        int n = nt * 8 + g;
        int k0 = kc * 16 + 2 * tig;
        g_W2p[i] = make_uint2(packbf(w2[k0 * 64 + n], w2[(k0 + 1) * 64 + n]),
                              packbf(w2[(k0 + 8) * 64 + n], w2[(k0 + 9) * 64 + n]));
    }
    for (int i = tid; i < 4 * 32; i += 256) {            // W3 (64x8)
        int lane = i & 31;
        int kc = i >> 5;
        int g = lane >> 2, tig = lane & 3;
        int k0 = kc * 16 + 2 * tig;
        g_W3p[i] = make_uint2(packbf(w3[k0 * 8 + g], w3[(k0 + 1) * 8 + g]),
                              packbf(w3[(k0 + 8) * 8 + g], w3[(k0 + 9) * 8 + g]));
    }
}

// ======== prologue/epilogue macros (MUFU everywhere, bit-safe) =================
#define SCAN_B2()                                                          \
  { float t3     = tanhA(fmaf(-10.0f, wd, y10B));                          \
    float inner2 = fmaf(t3, wd - yB, wd + yB);                             \
    float wdps   = wd + sd2B;                                              \
    wd = fmaf(-vB, inner2, wdps); }

#define SCAN_B1()                                                          \
  { float tw    = tanhA(fmaf(-10.0f, wl, rp10A));                          \
    float inner = fmaf(tw, wl - rpA, wl + rpA);                            \
    float wlpp  = wl + ppvzA;                                              \
    float et2   = uA * inner;                                              \
    wl = fmaf(-uA, inner, wlpp);                                           \
    float y   = rpA - et2;                                                 \
    float y10 = 10.0f * y;                                                 \
    float ty  = tanhA(y10);                                                \
    yB = y; y10B = y10; vB = fmaf(0.25f, ty, 0.25f); sd2B = ppvzA - et2; }

#define SCAN_A(QQ)                                                         \
  { float t1  = tanhA(fmaf(-10.0f, wu, (QQ).x));                           \
    float hd1 = fmaf(-0.5f, wu, (QQ).y);                                   \
    float z   = fmaf(t1, hd1, hd1);                                        \
    float wupp = wu + (QQ).z;                                              \
    wuS3 = wuS2; wuS2 = wuS1; wuS1 = wupp + z; wu = wuS1;                  \
    float tz  = tanhA(10.0f * z);                                          \
    float hz  = 0.5f * z;                                                  \
    float rp  = fmaf(tz, hz, hz);                                          \
    float rp10 = 10.0f * rp;                                               \
    float trp = tanhA(rp10);                                               \
    uA = fmaf(0.25f, trp, 0.25f);                                          \
    rpA = rp; rp10A = rp10; ppvzA = (QQ).z + z; }

// ======== main body: 3 chain tanh on MUFU, 3 off-chain tanh via SMEM table =====
#define IBODY(I, SLOT, STORE)                                              \
  { float4 qq = q##SLOT;                                                   \
    q##SLOT = pp[((I) + 6) * B_];                                          \
    float a_arg = fmaf(-10.0f, wu, qq.x);                                  \
    float b1arg = fmaf(-10.0f, wl, rp10A);                                 \
    float b2arg = fmaf(-10.0f, wd, y10B);                                  \
    float t1 = tanhA(a_arg);                                               \
    float tw = tanhA(b1arg);                                               \
    float t3 = tanhA(b2arg);                                               \
    float hd1  = fmaf(-0.5f, wu, qq.y);                                    \
    float wupp = wu + qq.z;                                                \
    float wdps = wd + sd2B;                                                \
    float wlpp = wl + ppvzA;                                               \
    float inner2 = fmaf(t3, wd - yB, wd + yB);                             \
    float wdP = wd;                                                        \
    wd = fmaf(-vB, inner2, wdps);                                          \
    float inner = fmaf(tw, wl - rpA, wl + rpA);                            \
    float et2   = uA * inner;                                              \
    wl = fmaf(-uA, inner, wlpp);                                           \
    float z = fmaf(t1, hd1, hd1);                                          \
    float y = rpA - et2;                                                   \
    float y10n = 10.0f * y;                                                \
    float tz = tanhT(tblc, 10.0f * z);                                     \
    float ty = tanhT(tblc, y10n);                                          \
    STORE                                                                  \
    sd2B = ppvzA - et2;                                                    \
    yB = y; y10B = y10n;                                                   \
    float wuN = wupp + z;                                                  \
    float hz  = 0.5f * z;                                                  \
    wuS3 = wuS2; wuS2 = wuS1; wuS1 = wuN; wu = wuN;                        \
    float rp   = fmaf(tz, hz, hz);                                         \
    vB = fmaf(0.25f, ty, 0.25f);                                           \
    float rp10n = 10.0f * rp;                                              \
    float trp = tanhT(tblc, rp10n);                                        \
    rpA = rp; rp10A = rp10n; ppvzA = qq.z + z;                             \
    uA = fmaf(0.25f, trp, 0.25f); }

#define NOSTORE
#define DOSTORE(I) wp[(((I) - 2) >> 1) * B_] = make_float4(wuS3, wdP, wuS2, wd);

// ---- fused persistent kernel: 1 block/SM -------------------------------------
// blocks 0,1: scan (128 threads, 1 warp/SMSP) ; blocks 2..151: persistent MLP
__global__ void __launch_bounds__(256)
main_kernel(const float* __restrict__ in,
            const float* __restrict__ b1v,
            const float* __restrict__ b2v,
            const float* __restrict__ b3v) {
    __shared__ uint2 sW1[32 * 32];
    __shared__ uint2 sW2[16 * 8 * 32];     // scan blocks: reused as tanh table
    __shared__ uint2 sW3[4 * 32];
    __shared__ float sB1[256];
    __shared__ float sB2[64];
    __shared__ float sB3[8];

    if (blockIdx.x < 2) {
        // fill tanh table: 4096 x float2 {V, 1-V^2} over [-8, 8), h = 1/256
        float2* tbl = reinterpret_cast<float2*>(sW2);
        for (int idx = threadIdx.x; idx < 4096; idx += blockDim.x) {
            float x = -8.0f + (float)idx * (1.0f / 256.0f);
            float v = tanhA(x);
            tbl[idx] = make_float2(v, fmaf(-v, v, 1.0f));
        }
        __syncthreads();
        if (threadIdx.x >= 128) return;
        const char* tblc = reinterpret_cast<const char*>(tbl);
        int b = blockIdx.x * 128 + threadIdx.x;       // 0..255
        const float4* __restrict__ pp = g_pp + b;
        float4* __restrict__ wp = g_w + b;

        float wu = 0.0f, wl = 0.0f, wd = 0.0f;
        float wuS1 = 0.0f, wuS2 = 0.0f, wuS3 = 0.0f;
        float rpA = 0.0f, rp10A = 0.0f, uA = 0.25f, ppvzA = 0.0f;
        float yB = 0.0f, y10B = 0.0f, vB = 0.25f, sd2B = 0.0f;

        float4 q0 = pp[0 * B_];
        float4 q1 = pp[1 * B_];
        float4 q2 = pp[2 * B_];
        float4 q3 = pp[3 * B_];
        float4 q4 = pp[4 * B_];
        float4 q5 = pp[5 * B_];

        // prologue: body 0 (A), body 1 (B1 + A)
        { float4 qq = q0; q0 = pp[6 * B_]; SCAN_A(qq); }
        { float4 qq = q1; q1 = pp[7 * B_]; SCAN_B1(); SCAN_A(qq); }

        // main: bodies 2..2047  (341 groups of 6; store at odd (I-2))
        for (int i = 2; i < T_; i += 6) {
            IBODY(i + 0, 2, NOSTORE);
            IBODY(i + 1, 3, DOSTORE(i + 1));
            IBODY(i + 2, 4, NOSTORE);
            IBODY(i + 3, 5, DOSTORE(i + 3));
            IBODY(i + 4, 0, NOSTORE);
            IBODY(i + 5, 1, DOSTORE(i + 5));
        }

        // epilogue: steps 2046, 2047
        SCAN_B2();
        float wd2046 = wd;
        SCAN_B1();
        SCAN_B2();
        wp[1023 * B_] = make_float4(wuS2, wd2046, wuS1, wd);
        return;
    }

    // ===================== persistent MLP ==================================
    for (int i = threadIdx.x; i < 32 * 32; i += 256)     sW1[i] = g_W1p[i];
    for (int i = threadIdx.x; i < 16 * 8 * 32; i += 256) sW2[i] = g_W2p[i];
    for (int i = threadIdx.x; i < 4 * 32; i += 256)      sW3[i] = g_W3p[i];
    if (threadIdx.x < 256) sB1[threadIdx.x] = b1v[threadIdx.x];
    if (threadIdx.x < 64)  sB2[threadIdx.x] = b2v[threadIdx.x];
    if (threadIdx.x < 8)   sB3[threadIdx.x] = b3v[threadIdx.x];
    __syncthreads();

    int warp = threadIdx.x >> 5;
    int lane = threadIdx.x & 31;
    int g    = lane >> 2, tig = lane & 3;
    int wg   = (blockIdx.x - 2) * 8 + warp;

    for (int tile = wg; tile < 32768; tile += (NBLK - 2) * 8) {
        int r0 = tile * 16 + g;
        int r1 = r0 + 8;

        unsigned int A0, A1, A2, A3;
        {
            const float* q0p = in + r0 * 20 + 5;
            const float* q1p = in + r1 * 20 + 5;
            float x0 = q0p[2 * tig],     x1 = q0p[2 * tig + 1];
            float y0 = q1p[2 * tig],     y1 = q1p[2 * tig + 1];
            float x2 = q0p[2 * tig + 8];
            float y2 = q1p[2 * tig + 8];
            float x3 = (tig < 3) ? q0p[2 * tig + 9] : 0.0f;
            float y3 = (tig < 3) ? q1p[2 * tig + 9] : 0.0f;
            A0 = packbf(x0, x1); A1 = packbf(y0, y1);
            A2 = packbf(x2, x3); A3 = packbf(y2, y3);
        }

        unsigned int h1a[16][4];
#pragma unroll
        for (int nt = 0; nt < 32; ++nt) {
            uint2 w = sW1[nt * 32 + lane];
            float c0 = 0.f, c1 = 0.f, c2 = 0.f, c3 = 0.f;
            mma16816(c0, c1, c2, c3, A0, A1, A2, A3, w.x, w.y);
            int   n0  = nt * 8 + 2 * tig;
            float bb0 = sB1[n0], bb1 = sB1[n0 + 1];
            c0 = tanhA(c0 + bb0); c1 = tanhA(c1 + bb1);
            c2 = tanhA(c2 + bb0); c3 = tanhA(c3 + bb1);
            h1a[nt >> 1][(nt & 1) * 2 + 0] = packbf(c0, c1);
            h1a[nt >> 1][(nt & 1) * 2 + 1] = packbf(c2, c3);
        }

        float acc[8][4];
#pragma unroll
        for (int nt = 0; nt < 8; ++nt) { acc[nt][0] = acc[nt][1] = acc[nt][2] = acc[nt][3] = 0.0f; }
#pragma unroll
        for (int kc = 0; kc < 16; ++kc) {
#pragma unroll
            for (int nt = 0; nt < 8; ++nt) {
                uint2 w = sW2[(kc * 8 + nt) * 32 + lane];
                mma16816(acc[nt][0], acc[nt][1], acc[nt][2], acc[nt][3],
                         h1a[kc][0], h1a[kc][1], h1a[kc][2], h1a[kc][3], w.x, w.y);
            }
        }
        unsigned int h2a[4][4];
#pragma unroll
        for (int nt = 0; nt < 8; ++nt) {
            int   n0  = nt * 8 + 2 * tig;
            float bb0 = sB2[n0], bb1 = sB2[n0 + 1];
            float c0 = tanhA(acc[nt][0] + bb0), c1 = tanhA(acc[nt][1] + bb1);
            float c2 = tanhA(acc[nt][2] + bb0), c3 = tanhA(acc[nt][3] + bb1);
            h2a[nt >> 1][(nt & 1) * 2 + 0] = packbf(c0, c1);
            h2a[nt >> 1][(nt & 1) * 2 + 1] = packbf(c2, c3);
        }

        float p0 = 0.f, p1 = 0.f, p2 = 0.f, p3 = 0.f;
#pragma unroll
        for (int kc = 0; kc < 4; ++kc) {
            uint2 w = sW3[kc * 32 + lane];
            mma16816(p0, p1, p2, p3, h2a[kc][0], h2a[kc][1], h2a[kc][2], h2a[kc][3], w.x, w.y);
        }
        int   n0  = 2 * tig;
        float bb0 = sB3[n0], bb1 = sB3[n0 + 1];
        p0 = sigm1(p0 + bb0);
        p1 = sigm1(p1 + bb1);
        p2 = sigm1(p2 + bb0);
        p3 = sigm1(p3 + bb1);
        *reinterpret_cast<float2*>(&g_params[r0 * 8 + n0]) = make_float2(p0, p1);
        *reinterpret_cast<float2*>(&g_params[r1 * 8 + n0]) = make_float2(p2, p3);
    }
}

// ---- final pointwise: runoff + partition (reference's swapped args!) ----------
__global__ void final_kernel(float* __restrict__ out) {
    int r = blockIdx.x * 256 + threadIdx.x;     // r = b*T + t
    int b = r >> 11, t = r & 2047;
    float4 wv = g_w[(t >> 1) * B_ + b];
    float wu = (t & 1) ? wv.z : wv.x;
    float wd = (t & 1) ? wv.w : wv.y;
    float p  = g_p[r];
    float4 q0 = *reinterpret_cast<const float4*>(&g_params[r * 8]);
    float4 q1 = *reinterpret_cast<const float4*>(&g_params[r * 8 + 4]);
    float wum = q0.x, wlm = q0.y, wdm = q0.z, bb = q0.w;
    float cc  = q1.x, k1 = q1.y, k2 = q1.z, k3 = q1.w;

    // reference calls _runoff(wu, wd, wl, p, wum, wdm, wlm, b, c)
    float wum_s = wum * 19.9f + 0.1f;
    float wlm_s = wdm * 30.0f + 60.0f;   // inner wlm <- outer wdm
    float wdm_s = wlm * 60.0f + 60.0f;   // inner wdm <- outer wlm
    float c_s   = cc * 0.19f + 0.01f;
    float b_s   = bb * 0.3f + 0.1f;
    float wt    = wum_s + wlm_s + wdm_s;
    float iwt   = __frcp_rn(wt);
    float u = wu * iwt;                  // inner wu
    float v = wd * iwt;                  // inner wl <- outer wd
    float s = c_s * u * u + b_s * v * v;
    float d = p - s;
    float runoff = heav(10.0f * d) * d;

    float k1s = k1 * 0.69f + 0.01f;
    float k2s = k2 * 0.69f + 0.01f;
    float k3s = k3 * 0.89f + 0.01f;
    float sr  = k1s * runoff;
    float itf = k2s * (runoff - sr);
    float bf  = k3s * (runoff - sr - itf);
    out[r] = sr + 0.5f * itf + 0.25f * bf;
}

extern "C" void kernel_launch(void* const* d_in, const int* in_sizes, int n_in,
                              void* d_out, int out_size) {
    const float* in  = (const float*)d_in[0];
    const float* w1  = (const float*)d_in[1];
    const float* b1  = (const float*)d_in[2];
    const float* w2  = (const float*)d_in[3];
    const float* b2  = (const float*)d_in[4];
    const float* w3  = (const float*)d_in[5];
    const float* b3  = (const float*)d_in[6];
    float* out = (float*)d_out;
    prep_kernel<<<513, 256>>>(in, w1, w2, w3);
    main_kernel<<<NBLK, 256>>>(in, b1, b2, b3);
    final_kernel<<<2048, 256>>>(out);
}